// round 11
// baseline (speedup 1.0000x reference)
#include <cuda_runtime.h>
#include <cuda_fp16.h>
#include <cstdint>

#define NB   64
#define NC   256
#define NCI  128
#define NTOK 256
#define NH   64

// -------------------- device scratch --------------------
__device__ float  g_xp   [NB * NC  * NTOK];  // pooled fp32 [b][c][tok] (residual)
__device__ __half g_xpt  [NB * NTOK * NC];   // pooled fp16 [b][tok][c]
__device__ __half g_Wch  [256 * NC];         // theta|phi weights fp16 [r][c]
__device__ __half g_gwh  [NCI * NC];         // fp16 [cc][c]
__device__ __half g_owh  [NC * NCI];         // fp16 [C][cc]
__device__ float  g_btp  [256];              // theta_b|phi_b fp32
__device__ __half g_proj [NB * NTOK * 256];  // [tok][r] fp16 (theta 0-127 | phi 128-255)
__device__ __half g_g    [NB * NCI * NTOK];  // [cc][j] fp16
__device__ float  g_logit[NB * NTOK * NTOK]; // [i][j] fp32 logits
__device__ __half g_attn [NB * NTOK * NTOK]; // [i][j] fp16 softmaxed
__device__ __half g_agg  [NB * NTOK * NCI];  // [i][cc] fp16

// -------------------- helpers --------------------
__device__ __forceinline__ void mma_f16(float (&c)[4],
                                        uint32_t a0, uint32_t a1, uint32_t a2, uint32_t a3,
                                        uint32_t b0, uint32_t b1) {
    asm volatile(
        "mma.sync.aligned.m16n8k16.row.col.f32.f16.f16.f32 "
        "{%0,%1,%2,%3},{%4,%5,%6,%7},{%8,%9},{%0,%1,%2,%3};\n"
        : "+f"(c[0]), "+f"(c[1]), "+f"(c[2]), "+f"(c[3])
        : "r"(a0), "r"(a1), "r"(a2), "r"(a3), "r"(b0), "r"(b1));
}
#define CPA(dst, src) asm volatile("cp.async.cg.shared.global [%0], [%1], 16;" :: "r"(dst), "l"(src))
#define CPC()         asm volatile("cp.async.commit_group;")
#define CPW(n)        asm volatile("cp.async.wait_group %0;" :: "n"(n))

// -------------------- prep: fp32->fp16 weight conversion + bias concat --------------------
__global__ void prep_kernel(const float* __restrict__ tw, const float* __restrict__ tb,
                            const float* __restrict__ pw, const float* __restrict__ pb,
                            const float* __restrict__ gw, const float* __restrict__ ow) {
    int idx = blockIdx.x * 256 + threadIdx.x;   // < 131072
    if (idx < 65536) {
        int r = idx >> 8;
        g_Wch[idx] = __float2half_rn((r < 128) ? tw[idx] : pw[idx - 32768]);
        if (idx < 256) g_btp[idx] = (idx < 128) ? tb[idx] : pb[idx - 128];
    } else if (idx < 98304) {
        int j = idx - 65536;
        g_gwh[j] = __float2half_rn(gw[j]);
    } else {
        int j = idx - 98304;
        g_owh[j] = __float2half_rn(ow[j]);
    }
}

// -------------------- pool: xp fp32 [c][tok] + xpt fp16 [tok][c] --------------------
__global__ void __launch_bounds__(256) pool_kernel(const float* __restrict__ x) {
    __shared__ float tile[32][257];
    int b = blockIdx.y, c0 = blockIdx.x << 5;
    int t = threadIdx.x;                  // tok
    int ph = t >> 4, pw = t & 15;
    for (int ci = 0; ci < 32; ci++) {
        int c = c0 + ci;
        const float* base = x + (((long)b * NC + c) * NH + ph * 4) * NH + pw * 4;
        float s = 0.f;
#pragma unroll
        for (int r = 0; r < 4; r++) {
            float4 v = *(const float4*)(base + r * NH);
            s += v.x + v.y + v.z + v.w;
        }
        s *= 0.0625f;
        g_xp[((long)b * NC + c) * NTOK + t] = s;
        tile[ci][t] = s;
    }
    __syncthreads();
#pragma unroll
    for (int rep = 0; rep < 8; rep++) {
        int u = rep * 256 + t;
        int tok = u >> 3, cq = (u & 7) << 2;   // 4 channels per 8B write
        __half2 h0 = __floats2half2_rn(tile[cq][tok],     tile[cq + 1][tok]);
        __half2 h1 = __floats2half2_rn(tile[cq + 2][tok], tile[cq + 3][tok]);
        __half2* dst = (__half2*)&g_xpt[((long)b * NTOK + tok) * NC + c0 + cq];
        dst[0] = h0; dst[1] = h1;
    }
}

// -------------------- fp16 GEMM: BM=64, BN=128, BK=32, 4-stage cp.async --------------------
// C[m][n] = sum_k A[m][k]*B[n][k], A/B fp16 k-contiguous.
// 256 thr = 8 warps, 2(M)x4(N), warp tile 32x32 (mt=2, nt=4), mma m16n8k16.
// smem row stride 40 fp16 (20 words; 20*gr+tc mod 32 bijective -> conflict-free).
// EPI 0: fp32 store (logits)  1: fp16 +bias[n]  2: fp16 +bias[m]  4: fp16 plain
// EPI 3: fp32 +bias[m]+resid, nearest 4x4 upsample -> dout
template<int EPI>
__global__ void __launch_bounds__(256, 3) hgemm(
    const __half* __restrict__ Ag, const __half* __restrict__ Bg, void* __restrict__ Cg,
    int lda, int ldb, int ldc, int K,
    long aB, long bB, long cB,
    const float* __restrict__ bias, const float* __restrict__ resid, float* __restrict__ dout)
{
    constexpr int SK   = 40;              // fp16 per smem row
    constexpr int AH   = 64 * SK;         // fp16 per A stage (2560)
    constexpr int BH   = 128 * SK;        // fp16 per B stage (5120)
    constexpr int STGH = AH + BH;         // 7680 fp16 = 15360 B

    extern __shared__ __half smem[];      // 4 stages
    uint32_t su = (uint32_t)__cvta_generic_to_shared(smem);

    int b = blockIdx.z;
    const __half* A = Ag + (long)b * aB;
    const __half* B = Bg + (long)b * bB;
    int m0 = blockIdx.y << 6, n0 = blockIdx.x << 7;
    int tid = threadIdx.x;
    int lane = tid & 31, wid = tid >> 5;
    int wm = (wid & 1) << 5;              // 0,32
    int wn = (wid >> 1) << 5;             // 0,32,64,96
    int gr = lane >> 2, tc = lane & 3;

    float acc[2][4][4] = {};
    int nk = K >> 5;

    int rA = tid >> 2, cA = tid & 3;      // A: row 0..63, chunk 0..3
    auto issue = [&](int slot, int t) {
        int k0 = t << 5;
        uint32_t base = su + slot * (STGH * 2);
        CPA(base + rA * 80 + cA * 16, A + (long)(m0 + rA) * lda + k0 + cA * 8);
        uint32_t bb = base + AH * 2;
#pragma unroll
        for (int i = 0; i < 2; i++) {
            int u = tid + i * 256;
            int rB = u >> 2, cb2 = u & 3;
            CPA(bb + rB * 80 + cb2 * 16, B + (long)(n0 + rB) * ldb + k0 + cb2 * 8);
        }
        CPC();
    };

    issue(0, 0); issue(1, 1); issue(2, 2);

    for (int t = 0; t < nk; t++) {
        CPW(2);
        __syncthreads();
        if (t + 3 < nk) issue((t + 3) & 3, t + 3);
        else            CPC();
        int slot = t & 3;
        const uint32_t* Aw = (const uint32_t*)(smem + slot * STGH);
        const uint32_t* Bw = (const uint32_t*)(smem + slot * STGH + AH);
#pragma unroll
        for (int ks = 0; ks < 2; ks++) {          // two k16 halves of BK=32
            int kw = ks * 8 + tc;                 // word offset in row
            uint32_t fa[2][4];
#pragma unroll
            for (int mt = 0; mt < 2; mt++) {
                int r0 = wm + (mt << 4) + gr;
                fa[mt][0] = Aw[r0 * 20 + kw];
                fa[mt][1] = Aw[(r0 + 8) * 20 + kw];
                fa[mt][2] = Aw[r0 * 20 + kw + 4];
                fa[mt][3] = Aw[(r0 + 8) * 20 + kw + 4];
            }
#pragma unroll
            for (int nt = 0; nt < 4; nt++) {
                int nrow = wn + (nt << 3) + gr;
                uint32_t fb0 = Bw[nrow * 20 + kw];
                uint32_t fb1 = Bw[nrow * 20 + kw + 4];
                mma_f16(acc[0][nt], fa[0][0], fa[0][1], fa[0][2], fa[0][3], fb0, fb1);
                mma_f16(acc[1][nt], fa[1][0], fa[1][1], fa[1][2], fa[1][3], fb0, fb1);
            }
        }
    }

    // -------- epilogue --------
    if (EPI == 0) {
        float* Cb = (float*)Cg + (long)b * cB;
#pragma unroll
        for (int mt = 0; mt < 2; mt++) {
            int r0 = m0 + wm + (mt << 4) + gr;
#pragma unroll
            for (int nt = 0; nt < 4; nt++) {
                int cn = n0 + wn + (nt << 3) + (tc << 1);
                *(float2*)(Cb + (long)r0 * ldc + cn)       = make_float2(acc[mt][nt][0], acc[mt][nt][1]);
                *(float2*)(Cb + (long)(r0 + 8) * ldc + cn) = make_float2(acc[mt][nt][2], acc[mt][nt][3]);
            }
        }
    } else if (EPI == 1 || EPI == 2 || EPI == 4) {
        __half* Cb = (__half*)Cg + (long)b * cB;
#pragma unroll
        for (int mt = 0; mt < 2; mt++) {
            int r0 = m0 + wm + (mt << 4) + gr;
            float bm0 = 0.f, bm1 = 0.f;
            if (EPI == 2) { bm0 = bias[r0]; bm1 = bias[r0 + 8]; }
#pragma unroll
            for (int nt = 0; nt < 4; nt++) {
                int cn = n0 + wn + (nt << 3) + (tc << 1);
                float bn0 = 0.f, bn1 = 0.f;
                if (EPI == 1) { bn0 = bias[cn]; bn1 = bias[cn + 1]; }
                *(__half2*)(Cb + (long)r0 * ldc + cn) =
                    __floats2half2_rn(acc[mt][nt][0] + bm0 + bn0, acc[mt][nt][1] + bm0 + bn1);
                *(__half2*)(Cb + (long)(r0 + 8) * ldc + cn) =
                    __floats2half2_rn(acc[mt][nt][2] + bm1 + bn0, acc[mt][nt][3] + bm1 + bn1);
            }
        }
    } else {
        // out conv: +bias[m] + resid, nearest 4x4 upsample -> dout (fp32)
#pragma unroll
        for (int mt = 0; mt < 2; mt++) {
#pragma unroll
            for (int rr = 0; rr < 2; rr++) {
                int c = m0 + wm + (mt << 4) + gr + (rr << 3);
                float bi = bias[c];
                const float* rrow = resid + ((long)b * NC + c) * NTOK;
                float* orow = dout + ((long)b * NC + c) * (NH * NH);
#pragma unroll
                for (int nt = 0; nt < 4; nt++) {
#pragma unroll
                    for (int jj = 0; jj < 2; jj++) {
                        int tok = n0 + wn + (nt << 3) + (tc << 1) + jj;
                        float v = acc[mt][nt][rr * 2 + jj] + bi + rrow[tok];
                        int ph = tok >> 4, pw = tok & 15;
                        float* o = orow + (ph * 4) * NH + pw * 4;
                        float4 f = make_float4(v, v, v, v);
                        *(float4*)(o)          = f;
                        *(float4*)(o + NH)     = f;
                        *(float4*)(o + 2 * NH) = f;
                        *(float4*)(o + 3 * NH) = f;
                    }
                }
            }
        }
    }
}

// -------------------- softmax: fp32 logits -> fp16 attn, row-major --------------------
__global__ void __launch_bounds__(256) softmax_row(const float* __restrict__ lg,
                                                   __half* __restrict__ at) {
    int b = blockIdx.y;
    int row = (blockIdx.x << 3) + (threadIdx.x >> 5);
    int lane = threadIdx.x & 31;
    const float* p = lg + ((long)b * NTOK + row) * NTOK;
    __half* q = at + ((long)b * NTOK + row) * NTOK;
    float v[8];
    float m = -1e30f;
#pragma unroll
    for (int k = 0; k < 8; k++) { v[k] = p[lane + (k << 5)]; m = fmaxf(m, v[k]); }
#pragma unroll
    for (int o = 16; o > 0; o >>= 1) m = fmaxf(m, __shfl_xor_sync(0xffffffffu, m, o));
    float s = 0.f;
#pragma unroll
    for (int k = 0; k < 8; k++) { v[k] = __expf(v[k] - m); s += v[k]; }
#pragma unroll
    for (int o = 16; o > 0; o >>= 1) s += __shfl_xor_sync(0xffffffffu, s, o);
    float inv = 1.f / s;
#pragma unroll
    for (int k = 0; k < 8; k++) q[lane + (k << 5)] = __float2half_rn(v[k] * inv);
}

// -------------------- launch --------------------
#define SMEMH (4 * 15360)   // 61440 B

extern "C" void kernel_launch(void* const* d_in, const int* in_sizes, int n_in,
                              void* d_out, int out_size) {
    (void)in_sizes; (void)n_in; (void)out_size;
    const float* x  = (const float*)d_in[0];
    const float* tw = (const float*)d_in[1];
    const float* tb = (const float*)d_in[2];
    const float* pw = (const float*)d_in[3];
    const float* pb = (const float*)d_in[4];
    const float* gw = (const float*)d_in[5];
    const float* gb = (const float*)d_in[6];
    const float* ow = (const float*)d_in[7];
    const float* ob = (const float*)d_in[8];
    float* out = (float*)d_out;

    float *xp, *btp, *logit;
    __half *xpt, *Wch, *gwh, *owh, *proj, *gg, *attn, *agg;
    cudaGetSymbolAddress((void**)&xp,    g_xp);
    cudaGetSymbolAddress((void**)&xpt,   g_xpt);
    cudaGetSymbolAddress((void**)&Wch,   g_Wch);
    cudaGetSymbolAddress((void**)&gwh,   g_gwh);
    cudaGetSymbolAddress((void**)&owh,   g_owh);
    cudaGetSymbolAddress((void**)&btp,   g_btp);
    cudaGetSymbolAddress((void**)&proj,  g_proj);
    cudaGetSymbolAddress((void**)&gg,    g_g);
    cudaGetSymbolAddress((void**)&logit, g_logit);
    cudaGetSymbolAddress((void**)&attn,  g_attn);
    cudaGetSymbolAddress((void**)&agg,   g_agg);

    cudaFuncSetAttribute(hgemm<0>, cudaFuncAttributeMaxDynamicSharedMemorySize, SMEMH);
    cudaFuncSetAttribute(hgemm<1>, cudaFuncAttributeMaxDynamicSharedMemorySize, SMEMH);
    cudaFuncSetAttribute(hgemm<2>, cudaFuncAttributeMaxDynamicSharedMemorySize, SMEMH);
    cudaFuncSetAttribute(hgemm<3>, cudaFuncAttributeMaxDynamicSharedMemorySize, SMEMH);
    cudaFuncSetAttribute(hgemm<4>, cudaFuncAttributeMaxDynamicSharedMemorySize, SMEMH);

    prep_kernel<<<512, 256>>>(tw, tb, pw, pb, gw, ow);
    pool_kernel<<<dim3(8, NB), 256>>>(x);

    // proj[tok][r] = xpt @ Wch^T + btp[n] : M=256, N=256, K=256
    hgemm<1><<<dim3(2, 4, NB), 256, SMEMH>>>(
        xpt, Wch, proj, 256, 256, 256, 256, 65536L, 0L, 65536L, btp, nullptr, nullptr);

    // g[cc][j] = gwh @ xpt^T + gb[m] : M=128, N=256, K=256
    hgemm<2><<<dim3(2, 2, NB), 256, SMEMH>>>(
        gwh, xpt, gg, 256, 256, 256, 256, 0L, 65536L, 32768L, gb, nullptr, nullptr);

    // logits[i][j] = theta @ phi^T (fp32 out) : M=256, N=256, K=128
    hgemm<0><<<dim3(2, 4, NB), 256, SMEMH>>>(
        proj, proj + 128, logit, 256, 256, 256, 128, 65536L, 65536L, 65536L,
        nullptr, nullptr, nullptr);

    softmax_row<<<dim3(32, NB), 256>>>(logit, attn);

    // agg[i][cc] = attn @ g^T : M=256, N=128, K=256
    hgemm<4><<<dim3(1, 4, NB), 256, SMEMH>>>(
        attn, gg, agg, 256, 256, 128, 256, 65536L, 32768L, 32768L,
        nullptr, nullptr, nullptr);

    // out[C][tok] = owh @ agg^T + ob[m] + xp, upsample -> d_out : M=256, N=256, K=128
    hgemm<3><<<dim3(2, 4, NB), 256, SMEMH>>>(
        owh, agg, nullptr, 128, 128, 0, 128, 0L, 32768L, 0L, ob, xp, out);
}

// round 12
// speedup vs baseline: 1.0199x; 1.0199x over previous
#include <cuda_runtime.h>
#include <cuda_fp16.h>
#include <cstdint>

#define NB   64
#define NC   256
#define NCI  128
#define NTOK 256
#define NH   64

// -------------------- device scratch --------------------
__device__ float  g_xp   [NB * NC  * NTOK];  // pooled fp32 [b][c][tok] (residual)
__device__ __half g_xpt  [NB * NTOK * NC];   // pooled fp16 [b][tok][c]
__device__ __half g_Wch  [256 * NC];         // theta|phi weights fp16 [r][c]
__device__ __half g_gwh  [NCI * NC];         // fp16 [cc][c]
__device__ __half g_owh  [NC * NCI];         // fp16 [C][cc]
__device__ float  g_btp  [256];              // theta_b|phi_b fp32
__device__ __half g_proj [NB * NTOK * 256];  // [tok][r] (theta 0-127 | phi 128-255)
__device__ __half g_g    [NB * NCI * NTOK];  // [cc][j]
__device__ float  g_logit[NB * NTOK * NTOK]; // [i][j] fp32 logits
__device__ __half g_attn [NB * NTOK * NTOK]; // [i][j] fp16 softmaxed
__device__ __half g_agg  [NB * NTOK * NCI];  // [i][cc]

// -------------------- helpers --------------------
__device__ __forceinline__ void mma_f16(float (&c)[4],
                                        uint32_t a0, uint32_t a1, uint32_t a2, uint32_t a3,
                                        uint32_t b0, uint32_t b1) {
    asm volatile(
        "mma.sync.aligned.m16n8k16.row.col.f32.f16.f16.f32 "
        "{%0,%1,%2,%3},{%4,%5,%6,%7},{%8,%9},{%0,%1,%2,%3};\n"
        : "+f"(c[0]), "+f"(c[1]), "+f"(c[2]), "+f"(c[3])
        : "r"(a0), "r"(a1), "r"(a2), "r"(a3), "r"(b0), "r"(b1));
}
#define LDSM4(r0, r1, r2, r3, a) \
    asm volatile("ldmatrix.sync.aligned.m8n8.x4.shared.b16 {%0,%1,%2,%3}, [%4];" \
                 : "=r"(r0), "=r"(r1), "=r"(r2), "=r"(r3) : "r"(a))
#define CPA(dst, src) asm volatile("cp.async.cg.shared.global [%0], [%1], 16;" :: "r"(dst), "l"(src))
#define CPC()         asm volatile("cp.async.commit_group;")
#define CPW(n)        asm volatile("cp.async.wait_group %0;" :: "n"(n))

// -------------------- prep: fp32->fp16 weights + bias concat --------------------
__global__ void prep_kernel(const float* __restrict__ tw, const float* __restrict__ tb,
                            const float* __restrict__ pw, const float* __restrict__ pb,
                            const float* __restrict__ gw, const float* __restrict__ ow) {
    int idx = blockIdx.x * 256 + threadIdx.x;   // < 131072
    if (idx < 65536) {
        int r = idx >> 8;
        g_Wch[idx] = __float2half_rn((r < 128) ? tw[idx] : pw[idx - 32768]);
        if (idx < 256) g_btp[idx] = (idx < 128) ? tb[idx] : pb[idx - 128];
    } else if (idx < 98304) {
        int j = idx - 65536;
        g_gwh[j] = __float2half_rn(gw[j]);
    } else {
        int j = idx - 98304;
        g_owh[j] = __float2half_rn(ow[j]);
    }
}

// -------------------- pool: xp fp32 [c][tok] + xpt fp16 [tok][c] --------------------
__global__ void __launch_bounds__(256) pool_kernel(const float* __restrict__ x) {
    __shared__ float tile[32][257];
    int b = blockIdx.y, c0 = blockIdx.x << 5;
    int t = threadIdx.x;                  // tok
    int ph = t >> 4, pw = t & 15;
    for (int ci = 0; ci < 32; ci++) {
        int c = c0 + ci;
        const float* base = x + (((long)b * NC + c) * NH + ph * 4) * NH + pw * 4;
        float s = 0.f;
#pragma unroll
        for (int r = 0; r < 4; r++) {
            float4 v = *(const float4*)(base + r * NH);
            s += v.x + v.y + v.z + v.w;
        }
        s *= 0.0625f;
        g_xp[((long)b * NC + c) * NTOK + t] = s;
        tile[ci][t] = s;
    }
    __syncthreads();
#pragma unroll
    for (int rep = 0; rep < 8; rep++) {
        int u = rep * 256 + t;
        int tok = u >> 3, cq = (u & 7) << 2;
        __half2 h0 = __floats2half2_rn(tile[cq][tok],     tile[cq + 1][tok]);
        __half2 h1 = __floats2half2_rn(tile[cq + 2][tok], tile[cq + 3][tok]);
        __half2* dst = (__half2*)&g_xpt[((long)b * NTOK + tok) * NC + c0 + cq];
        dst[0] = h0; dst[1] = h1;
    }
}

// -------------------- fp16 GEMM: BM=128, BN=128, BK=32, ldmatrix fragments --------------------
// C[m][n] = sum_k A[m][k]*B[n][k], A/B fp16 k-contiguous.
// 256 thr = 8 warps, 4(M)x2(N), warp tile 32x64 (mt=2, nt=8), mma m16n8k16.
// smem row stride 40 fp16 = 80B: ldmatrix phases conflict-free (20r mod 32 bijective on octets).
// EPI 0: fp32 store  1: fp16 +bias[n]  2: fp16 +bias[m]  4: fp16 plain
// EPI 3: fp32 +bias[m]+resid, nearest 4x4 upsample -> dout
template<int EPI>
__global__ void __launch_bounds__(256, 2) hgemm(
    const __half* __restrict__ Ag, const __half* __restrict__ Bg, void* __restrict__ Cg,
    int lda, int ldb, int ldc, int K,
    long aB, long bB, long cB,
    const float* __restrict__ bias, const float* __restrict__ resid, float* __restrict__ dout)
{
    constexpr int SKB  = 80;                 // bytes per smem row (32 fp16 + pad)
    constexpr int AB   = 128 * SKB;          // A stage bytes (10240)
    constexpr int BB   = 128 * SKB;          // B stage bytes
    constexpr int STGB = AB + BB;            // 20480 B per stage

    extern __shared__ __half smem[];         // 4 stages
    uint32_t su = (uint32_t)__cvta_generic_to_shared(smem);

    int b = blockIdx.z;
    const __half* A = Ag + (long)b * aB;
    const __half* B = Bg + (long)b * bB;
    int m0 = blockIdx.y << 7, n0 = blockIdx.x << 7;
    int tid = threadIdx.x;
    int lane = tid & 31, wid = tid >> 5;
    int wm = (wid & 3) << 5;                 // 0,32,64,96
    int wn = (wid >> 2) << 6;                // 0,64
    int gr = lane >> 2, tc = lane & 3;

    float acc[2][8][4] = {};
    int nk = K >> 5;

    // ldmatrix lane base addresses (within a stage)
    uint32_t aAddr = su + (wm + (lane & 15)) * SKB + ((lane >> 4) << 4);
    uint32_t bAddr = su + AB + (wn + (lane & 7) + ((lane >> 4) << 3)) * SKB
                   + (((lane >> 3) & 1) << 4);

    // staging: 4 chunks of 16B per row; u = tid + i*256 -> row u>>2, chunk u&3
    int rS = tid >> 2, cS = tid & 3;
    auto issue = [&](int slot, int t) {
        int k0 = t << 5;
        uint32_t base = su + slot * STGB;
        CPA(base + rS * SKB + cS * 16,      A + (long)(m0 + rS) * lda + k0 + cS * 8);
        CPA(base + (rS + 64) * SKB + cS * 16, A + (long)(m0 + rS + 64) * lda + k0 + cS * 8);
        uint32_t bb = base + AB;
        CPA(bb + rS * SKB + cS * 16,        B + (long)(n0 + rS) * ldb + k0 + cS * 8);
        CPA(bb + (rS + 64) * SKB + cS * 16, B + (long)(n0 + rS + 64) * ldb + k0 + cS * 8);
        CPC();
    };

    issue(0, 0); issue(1, 1); issue(2, 2);

    for (int t = 0; t < nk; t++) {
        CPW(2);
        __syncthreads();
        if (t + 3 < nk) issue((t + 3) & 3, t + 3);
        else            CPC();
        uint32_t so = (uint32_t)(t & 3) * STGB;
#pragma unroll
        for (int ks = 0; ks < 2; ks++) {
            uint32_t ko = ks << 5;           // +32 bytes per k16 step
            uint32_t fa[2][4];
            LDSM4(fa[0][0], fa[0][1], fa[0][2], fa[0][3], aAddr + so + ko);
            LDSM4(fa[1][0], fa[1][1], fa[1][2], fa[1][3], aAddr + so + ko + 16 * SKB);
#pragma unroll
            for (int p = 0; p < 4; p++) {    // n-tile pairs {0,1},{2,3},{4,5},{6,7}
                uint32_t b0, b1, b2, b3;
                LDSM4(b0, b1, b2, b3, bAddr + so + ko + p * 16 * SKB);
                mma_f16(acc[0][2 * p],     fa[0][0], fa[0][1], fa[0][2], fa[0][3], b0, b1);
                mma_f16(acc[1][2 * p],     fa[1][0], fa[1][1], fa[1][2], fa[1][3], b0, b1);
                mma_f16(acc[0][2 * p + 1], fa[0][0], fa[0][1], fa[0][2], fa[0][3], b2, b3);
                mma_f16(acc[1][2 * p + 1], fa[1][0], fa[1][1], fa[1][2], fa[1][3], b2, b3);
            }
        }
    }

    // -------- epilogue --------
    if (EPI == 0) {
        float* Cb = (float*)Cg + (long)b * cB;
#pragma unroll
        for (int mt = 0; mt < 2; mt++) {
            int r0 = m0 + wm + (mt << 4) + gr;
#pragma unroll
            for (int nt = 0; nt < 8; nt++) {
                int cn = n0 + wn + (nt << 3) + (tc << 1);
                *(float2*)(Cb + (long)r0 * ldc + cn)       = make_float2(acc[mt][nt][0], acc[mt][nt][1]);
                *(float2*)(Cb + (long)(r0 + 8) * ldc + cn) = make_float2(acc[mt][nt][2], acc[mt][nt][3]);
            }
        }
    } else if (EPI == 1 || EPI == 2 || EPI == 4) {
        __half* Cb = (__half*)Cg + (long)b * cB;
#pragma unroll
        for (int mt = 0; mt < 2; mt++) {
            int r0 = m0 + wm + (mt << 4) + gr;
            float bm0 = 0.f, bm1 = 0.f;
            if (EPI == 2) { bm0 = bias[r0]; bm1 = bias[r0 + 8]; }
#pragma unroll
            for (int nt = 0; nt < 8; nt++) {
                int cn = n0 + wn + (nt << 3) + (tc << 1);
                float bn0 = 0.f, bn1 = 0.f;
                if (EPI == 1) { bn0 = bias[cn]; bn1 = bias[cn + 1]; }
                *(__half2*)(Cb + (long)r0 * ldc + cn) =
                    __floats2half2_rn(acc[mt][nt][0] + bm0 + bn0, acc[mt][nt][1] + bm0 + bn1);
                *(__half2*)(Cb + (long)(r0 + 8) * ldc + cn) =
                    __floats2half2_rn(acc[mt][nt][2] + bm1 + bn0, acc[mt][nt][3] + bm1 + bn1);
            }
        }
    } else {
        // out conv: +bias[m] + resid, nearest 4x4 upsample -> dout (fp32)
#pragma unroll
        for (int mt = 0; mt < 2; mt++) {
#pragma unroll
            for (int rr = 0; rr < 2; rr++) {
                int c = m0 + wm + (mt << 4) + gr + (rr << 3);
                float bi = bias[c];
                const float* rrow = resid + ((long)b * NC + c) * NTOK;
                float* orow = dout + ((long)b * NC + c) * (NH * NH);
#pragma unroll
                for (int nt = 0; nt < 8; nt++) {
#pragma unroll
                    for (int jj = 0; jj < 2; jj++) {
                        int tok = n0 + wn + (nt << 3) + (tc << 1) + jj;
                        float v = acc[mt][nt][rr * 2 + jj] + bi + rrow[tok];
                        int ph = tok >> 4, pw = tok & 15;
                        float* o = orow + (ph * 4) * NH + pw * 4;
                        float4 f = make_float4(v, v, v, v);
                        *(float4*)(o)          = f;
                        *(float4*)(o + NH)     = f;
                        *(float4*)(o + 2 * NH) = f;
                        *(float4*)(o + 3 * NH) = f;
                    }
                }
            }
        }
    }
}

// -------------------- softmax: fp32 logits -> fp16 attn --------------------
__global__ void __launch_bounds__(256) softmax_row(const float* __restrict__ lg,
                                                   __half* __restrict__ at) {
    int b = blockIdx.y;
    int row = (blockIdx.x << 3) + (threadIdx.x >> 5);
    int lane = threadIdx.x & 31;
    const float* p = lg + ((long)b * NTOK + row) * NTOK;
    __half* q = at + ((long)b * NTOK + row) * NTOK;
    float v[8];
    float m = -1e30f;
#pragma unroll
    for (int k = 0; k < 8; k++) { v[k] = p[lane + (k << 5)]; m = fmaxf(m, v[k]); }
#pragma unroll
    for (int o = 16; o > 0; o >>= 1) m = fmaxf(m, __shfl_xor_sync(0xffffffffu, m, o));
    float s = 0.f;
#pragma unroll
    for (int k = 0; k < 8; k++) { v[k] = __expf(v[k] - m); s += v[k]; }
#pragma unroll
    for (int o = 16; o > 0; o >>= 1) s += __shfl_xor_sync(0xffffffffu, s, o);
    float inv = 1.f / s;
#pragma unroll
    for (int k = 0; k < 8; k++) q[lane + (k << 5)] = __float2half_rn(v[k] * inv);
}

// -------------------- launch --------------------
#define SMEMH (4 * 20480)   // 81920 B

extern "C" void kernel_launch(void* const* d_in, const int* in_sizes, int n_in,
                              void* d_out, int out_size) {
    (void)in_sizes; (void)n_in; (void)out_size;
    const float* x  = (const float*)d_in[0];
    const float* tw = (const float*)d_in[1];
    const float* tb = (const float*)d_in[2];
    const float* pw = (const float*)d_in[3];
    const float* pb = (const float*)d_in[4];
    const float* gw = (const float*)d_in[5];
    const float* gb = (const float*)d_in[6];
    const float* ow = (const float*)d_in[7];
    const float* ob = (const float*)d_in[8];
    float* out = (float*)d_out;

    float *xp, *btp, *logit;
    __half *xpt, *Wch, *gwh, *owh, *proj, *gg, *attn, *agg;
    cudaGetSymbolAddress((void**)&xp,    g_xp);
    cudaGetSymbolAddress((void**)&xpt,   g_xpt);
    cudaGetSymbolAddress((void**)&Wch,   g_Wch);
    cudaGetSymbolAddress((void**)&gwh,   g_gwh);
    cudaGetSymbolAddress((void**)&owh,   g_owh);
    cudaGetSymbolAddress((void**)&btp,   g_btp);
    cudaGetSymbolAddress((void**)&proj,  g_proj);
    cudaGetSymbolAddress((void**)&gg,    g_g);
    cudaGetSymbolAddress((void**)&logit, g_logit);
    cudaGetSymbolAddress((void**)&attn,  g_attn);
    cudaGetSymbolAddress((void**)&agg,   g_agg);

    cudaFuncSetAttribute(hgemm<0>, cudaFuncAttributeMaxDynamicSharedMemorySize, SMEMH);
    cudaFuncSetAttribute(hgemm<1>, cudaFuncAttributeMaxDynamicSharedMemorySize, SMEMH);
    cudaFuncSetAttribute(hgemm<2>, cudaFuncAttributeMaxDynamicSharedMemorySize, SMEMH);
    cudaFuncSetAttribute(hgemm<3>, cudaFuncAttributeMaxDynamicSharedMemorySize, SMEMH);
    cudaFuncSetAttribute(hgemm<4>, cudaFuncAttributeMaxDynamicSharedMemorySize, SMEMH);

    prep_kernel<<<512, 256>>>(tw, tb, pw, pb, gw, ow);
    pool_kernel<<<dim3(8, NB), 256>>>(x);

    // proj[tok][r] = xpt @ Wch^T + btp[n] : M=256, N=256, K=256 — grid 256
    hgemm<1><<<dim3(2, 2, NB), 256, SMEMH>>>(
        xpt, Wch, proj, 256, 256, 256, 256, 65536L, 0L, 65536L, btp, nullptr, nullptr);

    // g[cc][j] = gwh @ xpt^T + gb[m] : M=128, N=256, K=256 — grid 128
    hgemm<2><<<dim3(2, 1, NB), 256, SMEMH>>>(
        gwh, xpt, gg, 256, 256, 256, 256, 0L, 65536L, 32768L, gb, nullptr, nullptr);

    // logits[i][j] = theta @ phi^T (fp32) : M=256, N=256, K=128 — grid 256
    hgemm<0><<<dim3(2, 2, NB), 256, SMEMH>>>(
        proj, proj + 128, logit, 256, 256, 256, 128, 65536L, 65536L, 65536L,
        nullptr, nullptr, nullptr);

    softmax_row<<<dim3(32, NB), 256>>>(logit, attn);

    // agg[i][cc] = attn @ g^T : M=256, N=128, K=256 — grid 128
    hgemm<4><<<dim3(1, 2, NB), 256, SMEMH>>>(
        attn, gg, agg, 256, 256, 128, 256, 65536L, 32768L, 32768L,
        nullptr, nullptr, nullptr);

    // out[C][tok] = owh @ agg^T + ob[m] + xp, upsample -> d_out : M=256, N=256, K=128 — grid 256
    hgemm<3><<<dim3(2, 2, NB), 256, SMEMH>>>(
        owh, agg, nullptr, 128, 128, 0, 128, 0L, 32768L, 0L, ob, xp, out);
}